// round 10
// baseline (speedup 1.0000x reference)
#include <cuda_runtime.h>
#include <cstdint>

#define BSZ 4
#define D 16
#define MDIM 32
#define LTOT 81
#define NPASS2 (LTOT * BSZ)   // 324

#define ADD4(a, v) do { (a).x += (v).x; (a).y += (v).y; (a).z += (v).z; (a).w += (v).w; } while (0)

// Q[slab][jj][m], slab=(b,p1,p2) 0..1023, jj=j3*3+j4. 1.18 MB.
__device__ float g_Q[BSZ * D * D * 9 * MDIM];
__device__ float g_H[BSZ * LTOT];
__device__ unsigned int g_count = 0;

__device__ __forceinline__ uint32_t smem_u32(const void* p) {
    uint32_t a;
    asm("{ .reg .u64 t; cvta.to.shared.u64 t, %1; cvt.u32.u64 %0, t; }" : "=r"(a) : "l"(p));
    return a;
}
__device__ __forceinline__ void mbar_init(uint32_t mbar, uint32_t cnt) {
    asm volatile("mbarrier.init.shared.b64 [%0], %1;" :: "r"(mbar), "r"(cnt) : "memory");
}
__device__ __forceinline__ void mbar_expect_tx(uint32_t mbar, uint32_t bytes) {
    asm volatile("mbarrier.arrive.expect_tx.shared.b64 _, [%0], %1;" :: "r"(mbar), "r"(bytes) : "memory");
}
__device__ __forceinline__ void mbar_wait(uint32_t mbar, uint32_t parity) {
    asm volatile(
        "{\n\t.reg .pred P;\n\t"
        "WAIT_%=:\n\t"
        "mbarrier.try_wait.parity.acquire.cta.shared::cta.b64 P, [%0], %1, 0x989680;\n\t"
        "@!P bra WAIT_%=;\n\t}"
        :: "r"(mbar), "r"(parity) : "memory");
}
__device__ __forceinline__ void bulk_g2s(uint32_t dst, const void* src, uint32_t bytes, uint32_t mbar) {
    asm volatile(
        "cp.async.bulk.shared::cta.global.mbarrier::complete_tx::bytes [%0], [%1], %2, [%3];"
        :: "r"(dst), "l"(src), "r"(bytes), "r"(mbar) : "memory");
}
__device__ __forceinline__ void fence_proxy_async_cta() {
    asm volatile("fence.proxy.async.shared::cta;" ::: "memory");
}

// ---------------------------------------------------------------------------
// Pass 1 (TMA-pipelined, proven fastest): CTA k owns slabs 2k, 2k+1.
// 4-stage 8KB smem ring; 128 consumers reduce p3 in registers, p4 via smem.
// Position weight: p in class (p-1)%3 (if p>=1) and p%3 (if p<=14).
// ---------------------------------------------------------------------------
#define CHUNK_BYTES 8192
__global__ void __launch_bounds__(128) pass1_kernel(const char* __restrict__ arr) {
    __shared__ __align__(16) float buf[4][4 * 16 * 32];     // 4 x 8KB ring
    __shared__ float4 S[16][3][8];                           // [p4][j3][m4] 6KB
    __shared__ __align__(8) unsigned long long mbar[4];

    const int t  = threadIdx.x;
    const int m4 = t & 7;
    const int p4 = t >> 3;          // 0..15

    uint32_t mb[4];
#pragma unroll
    for (int q = 0; q < 4; ++q) mb[q] = smem_u32(&mbar[q]);

    if (t == 0) {
#pragma unroll
        for (int q = 0; q < 4; ++q) mbar_init(mb[q], 1);
    }
    __syncthreads();

    const int slab0 = blockIdx.x * 2;
    const char* __restrict__ src0 = arr + (size_t)slab0 * 32768;

    if (t == 0) {
#pragma unroll
        for (int q = 0; q < 4; ++q) {
            mbar_expect_tx(mb[q], CHUNK_BYTES);
            bulk_g2s(smem_u32(&buf[q][0]), src0 + q * CHUNK_BYTES, CHUNK_BYTES, mb[q]);
        }
    }

#pragma unroll
    for (int s = 0; s < 2; ++s) {
        const int slab = slab0 + s;
        float4 t0 = {0.f,0.f,0.f,0.f}, t1 = t0, t2 = t0;

#pragma unroll
        for (int q = 0; q < 4; ++q) {
            mbar_wait(mb[q], (uint32_t)s);

            const float4* __restrict__ bp = (const float4*)(&buf[q][0]) + p4 * 8 + m4;
#pragma unroll
            for (int k = 0; k < 4; ++k) {
                const int p3 = q * 4 + k;           // compile-time
                float4 v = bp[k * 128];
                if (p3 >= 1) {
                    const int ja = (p3 - 1) % 3;
                    if (ja == 0) ADD4(t0, v); else if (ja == 1) ADD4(t1, v); else ADD4(t2, v);
                }
                if (p3 <= 14) {
                    const int jb = p3 % 3;
                    if (jb == 0) ADD4(t0, v); else if (jb == 1) ADD4(t1, v); else ADD4(t2, v);
                }
            }
            __syncthreads();                        // all reads of buf[q] done
            if (s == 0 && t == 0) {                 // refill with slab1 chunk q
                fence_proxy_async_cta();
                mbar_expect_tx(mb[q], CHUNK_BYTES);
                bulk_g2s(smem_u32(&buf[q][0]),
                         src0 + 32768 + q * CHUNK_BYTES, CHUNK_BYTES, mb[q]);
            }
        }

        S[p4][0][m4] = t0;
        S[p4][1][m4] = t1;
        S[p4][2][m4] = t2;
        __syncthreads();

        if (t < 72) {               // t = jj*8 + mm : reduce p4 -> j4 classes
            const int mm = t & 7;
            const int jj = t >> 3;  // j3*3 + j4
            const int j4 = jj % 3;
            const int j3 = jj / 3;
            float4 qv = {0.f,0.f,0.f,0.f};
#pragma unroll
            for (int i = 0; i < 10; ++i) {
                const int p = 3 * (i >> 1) + j4 + (i & 1);
                ADD4(qv, S[p][j3][mm]);
            }
            ((float4*)g_Q)[slab * 72 + jj * 8 + mm] = qv;
        }
        __syncthreads();
    }
}

// ---------------------------------------------------------------------------
// Pass 2 (+fused finalize): block = (c,b), 256 threads.
//   E[c,m] = sum_n Bbasis[c,n]*M[n,m]
//   G[c,m] = sum over 100 (p1,p2) slices of Q (12-13 indep loads/warp)
//   H[b,c] = sum_m E[c,m]*G[c,m]
// Last block (atomic counter) computes out[b,n] = K*sum_c H[b,c]*Acoeff[n,c]
// and resets the counter (deterministic across graph replays).
// ---------------------------------------------------------------------------
__global__ void __launch_bounds__(256) pass2_kernel(const float* __restrict__ Mmat,
                                                    const float* __restrict__ Bbasis,
                                                    const float* __restrict__ Acoeff,
                                                    float* __restrict__ out) {
    __shared__ float E_s[32];
    __shared__ float part[8][32];
    __shared__ unsigned int rank_s;

    const int c  = blockIdx.x;
    const int b  = blockIdx.y;
    const int t  = threadIdx.x;
    const int lane = t & 31;
    const int wp   = t >> 5;

    const int j4 = c % 3;
    const int j3 = (c / 3) % 3;
    const int j2 = (c / 9) % 3;
    const int j1 = c / 27;
    const int jj = j3 * 3 + j4;

    if (t < 32) {
        float e = 0.f;
#pragma unroll
        for (int n = 0; n < MDIM; ++n)
            e += Bbasis[c * MDIM + n] * Mmat[n * MDIM + t];
        E_s[t] = e;
    }

    float g = 0.f;
    for (int k = wp; k < 100; k += 8) {
        const int i1 = k / 10;
        const int i2 = k % 10;
        const int p1 = 3 * (i1 >> 1) + j1 + (i1 & 1);
        const int p2 = 3 * (i2 >> 1) + j2 + (i2 & 1);
        g += g_Q[((((b * D + p1) * D + p2) * 9) + jj) * MDIM + lane];
    }
    part[wp][lane] = g;
    __syncthreads();

    if (wp == 0) {
        float G = part[0][lane] + part[1][lane] + part[2][lane] + part[3][lane]
                + part[4][lane] + part[5][lane] + part[6][lane] + part[7][lane];
        float h = E_s[lane] * G;
#pragma unroll
        for (int o = 16; o; o >>= 1)
            h += __shfl_xor_sync(0xffffffffu, h, o);
        if (lane == 0) g_H[b * LTOT + c] = h;
    }
    __syncthreads();

    // Last-block finalize (R3-proven pattern).
    if (t == 0) {
        __threadfence();
        rank_s = atomicAdd(&g_count, 1u);
    }
    __syncthreads();

    if (rank_s == (unsigned)(NPASS2 - 1)) {
        __threadfence();
        if (t < 128) {
            const int bb = t >> 5;
            const int n  = t & 31;
            const float K = 1.0f / (16.0f * 50625.0f);
            float s = 0.f;
#pragma unroll
            for (int cc = 0; cc < LTOT; ++cc)
                s += g_H[bb * LTOT + cc] * Acoeff[n * LTOT + cc];
            out[bb * MDIM + n] = s * K;
        }
        if (t == 0) g_count = 0;   // reset for next graph replay
    }
}

extern "C" void kernel_launch(void* const* d_in, const int* in_sizes, int n_in,
                              void* d_out, int out_size) {
    const char* arr     = (const char*)d_in[0];    // [4,16,16,16,16,32] f32
    const float* Mmat   = (const float*)d_in[1];   // [32,32]
    const float* Acoeff = (const float*)d_in[2];   // [32,81]
    const float* Bbasis = (const float*)d_in[3];   // [81,32]
    float* out = (float*)d_out;                    // [4,32]

    pass1_kernel<<<512, 128>>>(arr);               // 2 slabs per CTA

    dim3 g2(LTOT, BSZ);                            // (c, b) = 324 blocks
    pass2_kernel<<<g2, 256>>>(Mmat, Bbasis, Acoeff, out);
}

// round 11
// speedup vs baseline: 1.6961x; 1.6961x over previous
#include <cuda_runtime.h>
#include <cstdint>

#define BSZ 4
#define D 16
#define MDIM 32
#define LTOT 81

#define ADD4(a, v) do { (a).x += (v).x; (a).y += (v).y; (a).z += (v).z; (a).w += (v).w; } while (0)

// Q[slab][jj][m], slab=(b,p1,p2) 0..1023, jj=j3*3+j4. 1.18 MB.
__device__ float g_Q[BSZ * D * D * 9 * MDIM];
__device__ float g_H[BSZ * LTOT];

__device__ __forceinline__ uint32_t smem_u32(const void* p) {
    uint32_t a;
    asm("{ .reg .u64 t; cvta.to.shared.u64 t, %1; cvt.u32.u64 %0, t; }" : "=r"(a) : "l"(p));
    return a;
}
__device__ __forceinline__ void mbar_init(uint32_t mbar, uint32_t cnt) {
    asm volatile("mbarrier.init.shared.b64 [%0], %1;" :: "r"(mbar), "r"(cnt) : "memory");
}
__device__ __forceinline__ void mbar_expect_tx(uint32_t mbar, uint32_t bytes) {
    asm volatile("mbarrier.arrive.expect_tx.shared.b64 _, [%0], %1;" :: "r"(mbar), "r"(bytes) : "memory");
}
__device__ __forceinline__ void mbar_wait(uint32_t mbar, uint32_t parity) {
    asm volatile(
        "{\n\t.reg .pred P;\n\t"
        "WAIT_%=:\n\t"
        "mbarrier.try_wait.parity.acquire.cta.shared::cta.b64 P, [%0], %1, 0x989680;\n\t"
        "@!P bra WAIT_%=;\n\t}"
        :: "r"(mbar), "r"(parity) : "memory");
}
__device__ __forceinline__ void bulk_g2s(uint32_t dst, const void* src, uint32_t bytes, uint32_t mbar) {
    asm volatile(
        "cp.async.bulk.shared::cta.global.mbarrier::complete_tx::bytes [%0], [%1], %2, [%3];"
        :: "r"(dst), "l"(src), "r"(bytes), "r"(mbar) : "memory");
}
__device__ __forceinline__ void fence_proxy_async_cta() {
    asm volatile("fence.proxy.async.shared::cta;" ::: "memory");
}

// ---------------------------------------------------------------------------
// Pass 1 (TMA-pipelined, proven fastest): CTA k owns slabs 2k, 2k+1.
// 4-stage 8KB smem ring; 128 consumers reduce p3 in registers, p4 via smem.
// Position weight: p in class (p-1)%3 (if p>=1) and p%3 (if p<=14).
// Triggers PDL completion after its final g_Q stores.
// ---------------------------------------------------------------------------
#define CHUNK_BYTES 8192
__global__ void __launch_bounds__(128) pass1_kernel(const char* __restrict__ arr) {
    __shared__ __align__(16) float buf[4][4 * 16 * 32];     // 4 x 8KB ring
    __shared__ float4 S[16][3][8];                           // [p4][j3][m4] 6KB
    __shared__ __align__(8) unsigned long long mbar[4];

    const int t  = threadIdx.x;
    const int m4 = t & 7;
    const int p4 = t >> 3;          // 0..15

    uint32_t mb[4];
#pragma unroll
    for (int q = 0; q < 4; ++q) mb[q] = smem_u32(&mbar[q]);

    if (t == 0) {
#pragma unroll
        for (int q = 0; q < 4; ++q) mbar_init(mb[q], 1);
    }
    __syncthreads();

    const int slab0 = blockIdx.x * 2;
    const char* __restrict__ src0 = arr + (size_t)slab0 * 32768;

    if (t == 0) {
#pragma unroll
        for (int q = 0; q < 4; ++q) {
            mbar_expect_tx(mb[q], CHUNK_BYTES);
            bulk_g2s(smem_u32(&buf[q][0]), src0 + q * CHUNK_BYTES, CHUNK_BYTES, mb[q]);
        }
    }

#pragma unroll
    for (int s = 0; s < 2; ++s) {
        const int slab = slab0 + s;
        float4 t0 = {0.f,0.f,0.f,0.f}, t1 = t0, t2 = t0;

#pragma unroll
        for (int q = 0; q < 4; ++q) {
            mbar_wait(mb[q], (uint32_t)s);

            const float4* __restrict__ bp = (const float4*)(&buf[q][0]) + p4 * 8 + m4;
#pragma unroll
            for (int k = 0; k < 4; ++k) {
                const int p3 = q * 4 + k;           // compile-time
                float4 v = bp[k * 128];
                if (p3 >= 1) {
                    const int ja = (p3 - 1) % 3;
                    if (ja == 0) ADD4(t0, v); else if (ja == 1) ADD4(t1, v); else ADD4(t2, v);
                }
                if (p3 <= 14) {
                    const int jb = p3 % 3;
                    if (jb == 0) ADD4(t0, v); else if (jb == 1) ADD4(t1, v); else ADD4(t2, v);
                }
            }
            __syncthreads();                        // all reads of buf[q] done
            if (s == 0 && t == 0) {                 // refill with slab1 chunk q
                fence_proxy_async_cta();
                mbar_expect_tx(mb[q], CHUNK_BYTES);
                bulk_g2s(smem_u32(&buf[q][0]),
                         src0 + 32768 + q * CHUNK_BYTES, CHUNK_BYTES, mb[q]);
            }
        }

        S[p4][0][m4] = t0;
        S[p4][1][m4] = t1;
        S[p4][2][m4] = t2;
        __syncthreads();

        if (t < 72) {               // t = jj*8 + mm : reduce p4 -> j4 classes
            const int mm = t & 7;
            const int jj = t >> 3;  // j3*3 + j4
            const int j4 = jj % 3;
            const int j3 = jj / 3;
            float4 qv = {0.f,0.f,0.f,0.f};
#pragma unroll
            for (int i = 0; i < 10; ++i) {
                const int p = 3 * (i >> 1) + j4 + (i & 1);
                ADD4(qv, S[p][j3][mm]);
            }
            ((float4*)g_Q)[slab * 72 + jj * 8 + mm] = qv;
        }
        __syncthreads();
    }

    // All g_Q writes for this CTA are done: release to dependent grid.
    cudaTriggerProgrammaticLaunchCompletion();
}

// ---------------------------------------------------------------------------
// Pass 2 (PDL consumer): block (c, b), 128 threads.
// Prologue (independent of g_Q): E[c,m] = sum_n Bbasis[c,n]*M[n,m].
// Then cudaGridDependencySynchronize(), then G from g_Q, H[b,c] out.
// ---------------------------------------------------------------------------
__global__ void __launch_bounds__(128) pass2_kernel(const float* __restrict__ Mmat,
                                                    const float* __restrict__ Bbasis) {
    __shared__ float E_s[32];
    __shared__ float part[4][32];

    const int c  = blockIdx.x;   // 0..80
    const int b  = blockIdx.y;   // 0..3
    const int t  = threadIdx.x;
    const int lane = t & 31;
    const int wp   = t >> 5;

    const int j4 = c % 3;
    const int j3 = (c / 3) % 3;
    const int j2 = (c / 9) % 3;
    const int j1 = c / 27;
    const int jj = j3 * 3 + j4;

    // ---- prologue: overlaps with pass1 execution ----
    if (t < 32) {
        float e = 0.f;
#pragma unroll
        for (int n = 0; n < MDIM; ++n)
            e += Bbasis[c * MDIM + n] * Mmat[n * MDIM + t];
        E_s[t] = e;
    }

    // ---- wait for pass1's g_Q ----
    cudaGridDependencySynchronize();

    float g = 0.f;
#pragma unroll
    for (int k = wp; k < 20; k += 4) {       // 5 independent loads per warp
        const int i  = k >> 1;               // p1-window index 0..9
        const int hh = k & 1;                // p2 half 0..1 (5 windows each)
        const int p1 = 3 * (i >> 1) + j1 + (i & 1);
        // sum the 10 p2 windows split in two halves of 5
#pragma unroll
        for (int u = 0; u < 5; ++u) {
            const int i2 = hh * 5 + u;
            const int p2 = 3 * (i2 >> 1) + j2 + (i2 & 1);
            g += g_Q[(((b * D + p1) * D + p2) * 9 + jj) * MDIM + lane];
        }
    }
    part[wp][lane] = g;
    __syncthreads();

    if (wp == 0) {
        float G = part[0][lane] + part[1][lane] + part[2][lane] + part[3][lane];
        float h = E_s[lane] * G;
#pragma unroll
        for (int o = 16; o; o >>= 1)
            h += __shfl_xor_sync(0xffffffffu, h, o);
        if (lane == 0) g_H[b * LTOT + c] = h;
    }

    cudaTriggerProgrammaticLaunchCompletion();
}

// ---------------------------------------------------------------------------
// Pass 3 (PDL consumer): stage Acoeff during pass2, then finish.
// out[b,n] = K * sum_c H[b,c] * Acoeff[n,c],  K = 1/(16 * 15^4)
// ---------------------------------------------------------------------------
__global__ void __launch_bounds__(128) pass3_kernel(const float* __restrict__ Acoeff,
                                                    float* __restrict__ out) {
    __shared__ float A_s[MDIM * LTOT];   // [n][c] 10.4 KB

    const int t = threadIdx.x;
    for (int i = t; i < MDIM * LTOT; i += 128)
        A_s[i] = Acoeff[i];
    __syncthreads();

    cudaGridDependencySynchronize();

    const int b = t >> 5;
    const int n = t & 31;
    const float K = 1.0f / (16.0f * 50625.0f);
    float s = 0.f;
#pragma unroll
    for (int c = 0; c < LTOT; ++c)
        s += g_H[b * LTOT + c] * A_s[n * LTOT + c];
    out[b * MDIM + n] = s * K;
}

extern "C" void kernel_launch(void* const* d_in, const int* in_sizes, int n_in,
                              void* d_out, int out_size) {
    const char* arr     = (const char*)d_in[0];    // [4,16,16,16,16,32] f32
    const float* Mmat   = (const float*)d_in[1];   // [32,32]
    const float* Acoeff = (const float*)d_in[2];   // [32,81]
    const float* Bbasis = (const float*)d_in[3];   // [81,32]
    float* out = (float*)d_out;                    // [4,32]

    pass1_kernel<<<512, 128>>>(arr);               // 2 slabs per CTA

    cudaLaunchAttribute attr[1];
    attr[0].id = cudaLaunchAttributeProgrammaticStreamSerialization;
    attr[0].val.programmaticStreamSerializationAllowed = 1;

    {   // pass2 with PDL
        cudaLaunchConfig_t cfg = {};
        cfg.gridDim  = dim3(LTOT, BSZ, 1);
        cfg.blockDim = dim3(128, 1, 1);
        cfg.dynamicSmemBytes = 0;
        cfg.stream = 0;
        cfg.attrs = attr;
        cfg.numAttrs = 1;
        cudaLaunchKernelEx(&cfg, pass2_kernel, Mmat, Bbasis);
    }
    {   // pass3 with PDL
        cudaLaunchConfig_t cfg = {};
        cfg.gridDim  = dim3(1, 1, 1);
        cfg.blockDim = dim3(128, 1, 1);
        cfg.dynamicSmemBytes = 0;
        cfg.stream = 0;
        cfg.attrs = attr;
        cfg.numAttrs = 1;
        cudaLaunchKernelEx(&cfg, pass3_kernel, Acoeff, out);
    }
}

// round 12
// speedup vs baseline: 1.9724x; 1.1629x over previous
#include <cuda_runtime.h>
#include <cstdint>

#define BSZ 4
#define D 16
#define MDIM 32
#define LTOT 81

#define ADD4(a, v) do { (a).x += (v).x; (a).y += (v).y; (a).z += (v).z; (a).w += (v).w; } while (0)

// Q[slab][jj][m], slab=(b,p1,p2) 0..1023, jj=j3*3+j4. 1.18 MB.
__device__ float g_Q[BSZ * D * D * 9 * MDIM];
__device__ float g_H[BSZ * LTOT];

__device__ __forceinline__ uint32_t smem_u32(const void* p) {
    uint32_t a;
    asm("{ .reg .u64 t; cvta.to.shared.u64 t, %1; cvt.u32.u64 %0, t; }" : "=r"(a) : "l"(p));
    return a;
}
__device__ __forceinline__ void mbar_init(uint32_t mbar, uint32_t cnt) {
    asm volatile("mbarrier.init.shared.b64 [%0], %1;" :: "r"(mbar), "r"(cnt) : "memory");
}
__device__ __forceinline__ void mbar_expect_tx(uint32_t mbar, uint32_t bytes) {
    asm volatile("mbarrier.arrive.expect_tx.shared.b64 _, [%0], %1;" :: "r"(mbar), "r"(bytes) : "memory");
}
__device__ __forceinline__ void mbar_wait(uint32_t mbar, uint32_t parity) {
    asm volatile(
        "{\n\t.reg .pred P;\n\t"
        "WAIT_%=:\n\t"
        "mbarrier.try_wait.parity.acquire.cta.shared::cta.b64 P, [%0], %1, 0x989680;\n\t"
        "@!P bra WAIT_%=;\n\t}"
        :: "r"(mbar), "r"(parity) : "memory");
}
__device__ __forceinline__ void bulk_g2s(uint32_t dst, const void* src, uint32_t bytes, uint32_t mbar) {
    asm volatile(
        "cp.async.bulk.shared::cta.global.mbarrier::complete_tx::bytes [%0], [%1], %2, [%3];"
        :: "r"(dst), "l"(src), "r"(bytes), "r"(mbar) : "memory");
}
__device__ __forceinline__ void fence_proxy_async_cta() {
    asm volatile("fence.proxy.async.shared::cta;" ::: "memory");
}

// ---------------------------------------------------------------------------
// Pass 1: CTA k owns slabs 2k, 2k+1 (8 chunks of 8KB). 6-stage smem ring:
// 6 chunks issued in prologue, chunks 6,7 issued after consuming chunks 0,1.
// Chunk i: slab = i/4, p3 = (i%4)*4 + k (compile-time). Thread = (m4, p4).
// Epilogues after chunks 3 and 7 reduce p4 -> j4 classes into g_Q.
// Position weight: p in class (p-1)%3 (if p>=1) and p%3 (if p<=14).
// ---------------------------------------------------------------------------
#define CHUNK_BYTES 8192
#define NSTAGE 6
__global__ void __launch_bounds__(128) pass1_kernel(const char* __restrict__ arr) {
    __shared__ __align__(16) float buf[NSTAGE][4 * 16 * 32];  // 6 x 8KB ring
    __shared__ float4 S[16][3][8];                             // [p4][j3][m4] 6KB
    __shared__ __align__(8) unsigned long long mbar[NSTAGE];

    const int t  = threadIdx.x;
    const int m4 = t & 7;
    const int p4 = t >> 3;          // 0..15

    uint32_t mb[NSTAGE];
#pragma unroll
    for (int q = 0; q < NSTAGE; ++q) mb[q] = smem_u32(&mbar[q]);

    if (t == 0) {
#pragma unroll
        for (int q = 0; q < NSTAGE; ++q) mbar_init(mb[q], 1);
    }
    __syncthreads();

    const int slab0 = blockIdx.x * 2;
    const char* __restrict__ src0 = arr + (size_t)slab0 * 32768;

    // Prologue: 6 chunks in flight immediately.
    if (t == 0) {
#pragma unroll
        for (int q = 0; q < NSTAGE; ++q) {
            mbar_expect_tx(mb[q], CHUNK_BYTES);
            bulk_g2s(smem_u32(&buf[q][0]), src0 + q * CHUNK_BYTES, CHUNK_BYTES, mb[q]);
        }
    }

    float4 t0 = {0.f,0.f,0.f,0.f}, t1 = t0, t2 = t0;

#pragma unroll
    for (int i = 0; i < 8; ++i) {
        const int stage  = (i < NSTAGE) ? i : (i - NSTAGE);
        const int parity = (i < NSTAGE) ? 0 : 1;
        mbar_wait(mb[stage], (uint32_t)parity);

        const float4* __restrict__ bp = (const float4*)(&buf[stage][0]) + p4 * 8 + m4;
#pragma unroll
        for (int k = 0; k < 4; ++k) {
            const int p3 = (i & 3) * 4 + k;        // compile-time
            float4 v = bp[k * 128];
            if (p3 >= 1) {
                const int ja = (p3 - 1) % 3;
                if (ja == 0) ADD4(t0, v); else if (ja == 1) ADD4(t1, v); else ADD4(t2, v);
            }
            if (p3 <= 14) {
                const int jb = p3 % 3;
                if (jb == 0) ADD4(t0, v); else if (jb == 1) ADD4(t1, v); else ADD4(t2, v);
            }
        }

        if (i < 2) {                 // refill stage i with chunk i+6
            __syncthreads();         // all reads of stage i complete
            if (t == 0) {
                fence_proxy_async_cta();
                mbar_expect_tx(mb[stage], CHUNK_BYTES);
                bulk_g2s(smem_u32(&buf[stage][0]),
                         src0 + (i + NSTAGE) * CHUNK_BYTES, CHUNK_BYTES, mb[stage]);
            }
        }

        if (i == 3 || i == 7) {      // epilogue for slab i/4
            const int slab = slab0 + (i >> 2);
            __syncthreads();         // prior S use (reduce) finished
            S[p4][0][m4] = t0;
            S[p4][1][m4] = t1;
            S[p4][2][m4] = t2;
            __syncthreads();

            if (t < 72) {            // t = jj*8 + mm : reduce p4 -> j4 classes
                const int mm = t & 7;
                const int jj = t >> 3;   // j3*3 + j4
                const int j4 = jj % 3;
                const int j3 = jj / 3;
                float4 qv = {0.f,0.f,0.f,0.f};
#pragma unroll
                for (int u = 0; u < 10; ++u) {
                    const int p = 3 * (u >> 1) + j4 + (u & 1);
                    ADD4(qv, S[p][j3][mm]);
                }
                ((float4*)g_Q)[slab * 72 + jj * 8 + mm] = qv;
            }
            t0 = make_float4(0.f, 0.f, 0.f, 0.f);
            t1 = t0;
            t2 = t0;
        }
    }

    // All g_Q writes for this CTA are done: release to dependent grid.
    cudaTriggerProgrammaticLaunchCompletion();
}

// ---------------------------------------------------------------------------
// Pass 2 (PDL consumer): block (c, b), 128 threads.
// Prologue (independent of g_Q): E[c,m] = sum_n Bbasis[c,n]*M[n,m].
// Then cudaGridDependencySynchronize(), then G from g_Q, H[b,c] out.
// ---------------------------------------------------------------------------
__global__ void __launch_bounds__(128) pass2_kernel(const float* __restrict__ Mmat,
                                                    const float* __restrict__ Bbasis) {
    __shared__ float E_s[32];
    __shared__ float part[4][32];

    const int c  = blockIdx.x;   // 0..80
    const int b  = blockIdx.y;   // 0..3
    const int t  = threadIdx.x;
    const int lane = t & 31;
    const int wp   = t >> 5;

    const int j4 = c % 3;
    const int j3 = (c / 3) % 3;
    const int j2 = (c / 9) % 3;
    const int j1 = c / 27;
    const int jj = j3 * 3 + j4;

    // ---- prologue: overlaps with pass1 execution ----
    if (t < 32) {
        float e = 0.f;
#pragma unroll
        for (int n = 0; n < MDIM; ++n)
            e += Bbasis[c * MDIM + n] * Mmat[n * MDIM + t];
        E_s[t] = e;
    }

    // ---- wait for pass1's g_Q ----
    cudaGridDependencySynchronize();

    float g = 0.f;
#pragma unroll
    for (int k = wp; k < 20; k += 4) {       // 5 independent load groups per warp
        const int i  = k >> 1;               // p1-window index 0..9
        const int hh = k & 1;                // p2 half 0..1 (5 windows each)
        const int p1 = 3 * (i >> 1) + j1 + (i & 1);
#pragma unroll
        for (int u = 0; u < 5; ++u) {
            const int i2 = hh * 5 + u;
            const int p2 = 3 * (i2 >> 1) + j2 + (i2 & 1);
            g += g_Q[(((b * D + p1) * D + p2) * 9 + jj) * MDIM + lane];
        }
    }
    part[wp][lane] = g;
    __syncthreads();

    if (wp == 0) {
        float G = part[0][lane] + part[1][lane] + part[2][lane] + part[3][lane];
        float h = E_s[lane] * G;
#pragma unroll
        for (int o = 16; o; o >>= 1)
            h += __shfl_xor_sync(0xffffffffu, h, o);
        if (lane == 0) g_H[b * LTOT + c] = h;
    }

    cudaTriggerProgrammaticLaunchCompletion();
}

// ---------------------------------------------------------------------------
// Pass 3 (PDL consumer): stage Acoeff during pass2, then finish.
// out[b,n] = K * sum_c H[b,c] * Acoeff[n,c],  K = 1/(16 * 15^4)
// ---------------------------------------------------------------------------
__global__ void __launch_bounds__(128) pass3_kernel(const float* __restrict__ Acoeff,
                                                    float* __restrict__ out) {
    __shared__ float A_s[MDIM * LTOT];   // [n][c] 10.4 KB

    const int t = threadIdx.x;
    for (int i = t; i < MDIM * LTOT; i += 128)
        A_s[i] = Acoeff[i];
    __syncthreads();

    cudaGridDependencySynchronize();

    const int b = t >> 5;
    const int n = t & 31;
    const float K = 1.0f / (16.0f * 50625.0f);
    float s = 0.f;
#pragma unroll
    for (int c = 0; c < LTOT; ++c)
        s += g_H[b * LTOT + c] * A_s[n * LTOT + c];
    out[b * MDIM + n] = s * K;
}

extern "C" void kernel_launch(void* const* d_in, const int* in_sizes, int n_in,
                              void* d_out, int out_size) {
    const char* arr     = (const char*)d_in[0];    // [4,16,16,16,16,32] f32
    const float* Mmat   = (const float*)d_in[1];   // [32,32]
    const float* Acoeff = (const float*)d_in[2];   // [32,81]
    const float* Bbasis = (const float*)d_in[3];   // [81,32]
    float* out = (float*)d_out;                    // [4,32]

    pass1_kernel<<<512, 128>>>(arr);               // 2 slabs per CTA

    cudaLaunchAttribute attr[1];
    attr[0].id = cudaLaunchAttributeProgrammaticStreamSerialization;
    attr[0].val.programmaticStreamSerializationAllowed = 1;

    {   // pass2 with PDL
        cudaLaunchConfig_t cfg = {};
        cfg.gridDim  = dim3(LTOT, BSZ, 1);
        cfg.blockDim = dim3(128, 1, 1);
        cfg.dynamicSmemBytes = 0;
        cfg.stream = 0;
        cfg.attrs = attr;
        cfg.numAttrs = 1;
        cudaLaunchKernelEx(&cfg, pass2_kernel, Mmat, Bbasis);
    }
    {   // pass3 with PDL
        cudaLaunchConfig_t cfg = {};
        cfg.gridDim  = dim3(1, 1, 1);
        cfg.blockDim = dim3(128, 1, 1);
        cfg.dynamicSmemBytes = 0;
        cfg.stream = 0;
        cfg.attrs = attr;
        cfg.numAttrs = 1;
        cudaLaunchKernelEx(&cfg, pass3_kernel, Acoeff, out);
    }
}